// round 16
// baseline (speedup 1.0000x reference)
#include <cuda_runtime.h>
#include <cuda_bf16.h>
#include <cstdint>
#include <math.h>

// ---- problem constants ----
#define NB 4
#define NT 12
#define NV 512
#define NC 64
#define ND 8
#define NTS 3
#define NP 12
#define NL 4
#define NM (NTS*NV)   // 1536
#define NN (NT*NC)    // 768

// ---- scratch (device globals) ----
__device__ float g_hT[NL+1][NB*NT*NC*NV]; // h per layer, transposed [b][t][c][v]
__device__ float g_EbT[NL*NV*NV];         // [l][j][i]
__device__ float g_ept[NL*NB*NT*NTS];
__device__ float g_skips[NB*NV*4*NC];
__device__ float g_fswT[NL*NN*NC];
__device__ float g_g1wT[NL*NC*2*NC];
__device__ float g_goutT[256*512];
__device__ float g_outT[256*NP];
__device__ float g_upart[2][(size_t)NB*NT*NV*NC];         // split-K partial u
__device__ __nv_bfloat16 g_Ahi[(size_t)NL*NB*NV*NM];      // split A = mask*EbT
__device__ __nv_bfloat16 g_Alo[(size_t)NL*NB*NV*NM];
__device__ __nv_bfloat16 g_Bhi[2][(size_t)NB*NT*NC*NM];   // B = ept*h, parity by layer
__device__ __nv_bfloat16 g_Blo[2][(size_t)NB*NT*NC*NM];

__device__ __forceinline__ float sigm(float x) { return 1.0f/(1.0f+expf(-x)); }

__device__ __forceinline__ uint32_t smem_u32(const void* p) {
    uint32_t a;
    asm("{ .reg .u64 tmp; cvta.to.shared.u64 tmp, %1; cvt.u32.u64 %0, tmp; }"
        : "=r"(a) : "l"(p));
    return a;
}
__device__ __forceinline__ void ldmx4(uint32_t& r0, uint32_t& r1, uint32_t& r2, uint32_t& r3,
                                      uint32_t addr) {
    asm volatile("ldmatrix.sync.aligned.m8n8.x4.shared.b16 {%0,%1,%2,%3}, [%4];"
        : "=r"(r0), "=r"(r1), "=r"(r2), "=r"(r3) : "r"(addr));
}
__device__ __forceinline__ void mma16816(float* c, const uint32_t* a, const uint32_t* b) {
    asm volatile("mma.sync.aligned.m16n8k16.row.col.f32.bf16.bf16.f32 "
        "{%0,%1,%2,%3}, {%4,%5,%6,%7}, {%8,%9}, {%0,%1,%2,%3};"
        : "+f"(c[0]), "+f"(c[1]), "+f"(c[2]), "+f"(c[3])
        : "r"(a[0]), "r"(a[1]), "r"(a[2]), "r"(a[3]), "r"(b[0]), "r"(b[1]));
}
#define CP_ASYNC16(saddr, gptr) \
    asm volatile("cp.async.cg.shared.global [%0], [%1], 16;" :: "r"(saddr), "l"(gptr))
#define CP_COMMIT() asm volatile("cp.async.commit_group;" ::: "memory")
#define CP_WAIT1()  asm volatile("cp.async.wait_group 1;" ::: "memory")
#define CP_WAIT0()  asm volatile("cp.async.wait_group 0;" ::: "memory")

__device__ __forceinline__ void bsplit(float val, __nv_bfloat16& hi, __nv_bfloat16& lo) {
    hi = __float2bfloat16(val);
    lo = __float2bfloat16(val - __bfloat162float(hi));
}

// ---- merged: weight transposes + input layer (+ layer-0 B split, parity 0) ----
__global__ void k_init(const float* __restrict__ x, const float* __restrict__ Wi,
                       const float* __restrict__ bi,
                       const float* __restrict__ fs_w, const float* __restrict__ g1w,
                       const float* __restrict__ gout_w, const float* __restrict__ out_w) {
    if (blockIdx.x < 6144) {
        int idx = blockIdx.x*256 + threadIdx.x;
        int v = idx & 511;
        int c = (idx >> 9) & 63;
        int bt = idx >> 15;
        float h = x[bt*NV + v]*Wi[c] + bi[c];
        g_hT[0][idx] = h;
        int t = bt % NT, b = bt / NT;
        #pragma unroll
        for (int kw = 0; kw < NTS; kw++) {
            int tout = t + 2 - kw;
            if (tout < NT) {
                float ep = g_ept[(b*NT + tout)*NTS + kw];   // layer 0
                __nv_bfloat16 hi, lo;
                bsplit(ep*h, hi, lo);
                size_t off = ((size_t)(b*NT + tout)*NC + c)*NM + kw*512 + v;
                g_Bhi[0][off] = hi;
                g_Blo[0][off] = lo;
            }
        }
        return;
    }
    int idx = (blockIdx.x - 6144)*256 + threadIdx.x;
    if (idx < NL*NN*NC) {
        int l = idx / (NN*NC); int r = idx % (NN*NC); int ct = r >> 6; int oo = r & 63;
        g_fswT[idx] = fs_w[l*NC*NN + oo*NN + ct];
        return;
    }
    idx -= NL*NN*NC;
    if (idx < NL*NC*2*NC) {
        int l = idx / (NC*2*NC); int r = idx % (NC*2*NC); int c = r >> 7; int o = r & 127;
        g_g1wT[idx] = g1w[l*2*NC*NC + o*NC + c];
        return;
    }
    idx -= NL*NC*2*NC;
    if (idx < 256*512) {
        int c = idx >> 9; int o = idx & 511;
        g_goutT[idx] = gout_w[o*256 + c];
        return;
    }
    idx -= 256*512;
    if (idx < 256*NP) {
        int c = idx / NP; int p = idx % NP;
        g_outT[idx] = out_w[p*256 + c];
    }
}

// ---- merged: Ebase^T + (block 0) ept for all layers ----
__global__ void k_ebase2(const float* __restrict__ srpe, const float* __restrict__ sape,
                         const float* __restrict__ tape, const float* __restrict__ trpe,
                         const float* __restrict__ gc_mu, const float* __restrict__ gc_sig) {
    int l = blockIdx.y;
    int tid = threadIdx.x;
    int idx = blockIdx.x*256 + tid;
    int i = idx >> 9, j = idx & 511;
    const float* mu = gc_mu + l*6*ND;
    const float* sg = gc_sig + l*6*ND;
    float gs0 = 0.f, gs1 = 0.f, a = 0.f;
    const float* e = srpe + (size_t)idx*ND;
    #pragma unroll
    for (int dd = 0; dd < ND; dd++) {
        float e0 = sape[i*ND + dd] - mu[0*ND+dd];
        float e1 = sape[j*ND + dd] - mu[1*ND+dd];
        float e4 = e[dd] - mu[4*ND+dd];
        gs0 += -0.5f*e0*e0*sg[0*ND+dd]*sg[0*ND+dd];
        gs1 += -0.5f*e1*e1*sg[1*ND+dd]*sg[1*ND+dd];
        a   += -0.5f*e4*e4*sg[4*ND+dd]*sg[4*ND+dd];
    }
    g_EbT[l*NV*NV + j*NV + i] = expf(a + gs0 + gs1);

    if (blockIdx.x == 0) {
        __shared__ float gt2[NB*NT];
        __shared__ float gt3[NB*(NT+2)];
        __shared__ float gt5[NTS];
        if (tid < NB*NT) {
            float s = 0.f;
            #pragma unroll
            for (int dd = 0; dd < ND; dd++) {
                float dv = tape[tid*ND + dd] - mu[2*ND+dd];
                s += -0.5f*dv*dv*sg[2*ND+dd]*sg[2*ND+dd];
            }
            gt2[tid] = s;
        }
        if (tid < NB*(NT+2)) {
            int b = tid/(NT+2), tau = tid%(NT+2);
            float s = 0.f;
            #pragma unroll
            for (int dd = 0; dd < ND; dd++) {
                float ev = (tau < 2) ? 0.0f : tape[(b*NT + (tau-2))*ND + dd];
                float dv = ev - mu[3*ND+dd];
                s += -0.5f*dv*dv*sg[3*ND+dd]*sg[3*ND+dd];
            }
            gt3[tid] = s;
        }
        if (tid < NTS) {
            float s = 0.f;
            #pragma unroll
            for (int dd = 0; dd < ND; dd++) {
                float dv = trpe[tid*ND + dd] - mu[5*ND+dd];
                s += -0.5f*dv*dv*sg[5*ND+dd]*sg[5*ND+dd];
            }
            gt5[tid] = s;
        }
        __syncthreads();
        if (tid < NB*NT*NTS) {
            int k = tid % NTS; int bt = tid / NTS;
            int b = bt / NT, t = bt % NT;
            g_ept[l*NB*NT*NTS + tid] = expf(gt2[bt] + gt3[b*(NT+2) + t + k] + gt5[k]);
        }
    }
}

// ---- split A = mask*EbT into bf16 hi/lo ----
__global__ void k_asplit(const float* __restrict__ mask) {
    size_t gidx = (size_t)blockIdx.x*256 + threadIdx.x;
    size_t g = gidx;
    int mq = (int)(g % 384); g /= 384;
    int j  = (int)(g % 512);
    int b  = (int)(g / 512);
    int m = mq*4, i = m & 511;
    float4 mv = *(const float4*)(mask + (((size_t)b*NV + j)*NM + m));
    #pragma unroll
    for (int l = 0; l < NL; l++) {
        float4 ev = *(const float4*)(g_EbT + ((size_t)l*NV + j)*NV + i);
        float a[4] = {mv.x*ev.x, mv.y*ev.y, mv.z*ev.z, mv.w*ev.w};
        union { __nv_bfloat16 h[4]; uint2 u; } Hi, Lo;
        #pragma unroll
        for (int q = 0; q < 4; q++) bsplit(a[q], Hi.h[q], Lo.h[q]);
        size_t off = (((size_t)l*NB + b)*NV + j)*NM + m;
        *(uint2*)(g_Ahi + off) = Hi.u;
        *(uint2*)(g_Alo + off) = Lo.u;
    }
}

// ========== split-K pipelined warp-MMA graph-conv (BM=64, 128 thr) ===========
#define APITCH 40
#define ST_SZ 5120
#define OFF_AHI   512
#define OFF_ALO   15872
#define OFF_BHI   31232
#define OFF_BLO   46592
#define OFF_US    512
#define SMEM_TOTAL 61952
#define USP 76

__global__ void __launch_bounds__(128, 3) k_gconv_mma(int l) {
    extern __shared__ __align__(1024) char smem[];
    int bz = blockIdx.z;
    int b  = bz & 3;
    int kh = bz >> 2;
    int t  = blockIdx.x;
    int m0 = blockIdx.y * 64;
    int tid = threadIdx.x, wid = tid >> 5, lane = tid & 31;
    uint32_t sb = smem_u32(smem);

    const __nv_bfloat16* Ahig = g_Ahi + (((size_t)l*NB + b)*NV + m0)*NM;
    const __nv_bfloat16* Alog = g_Alo + (((size_t)l*NB + b)*NV + m0)*NM;
    const __nv_bfloat16* Bhig = g_Bhi[l & 1] + ((size_t)(b*NT + t)*NC)*NM;
    const __nv_bfloat16* Blog = g_Blo[l & 1] + ((size_t)(b*NT + t)*NC)*NM;

    float acc[8][4];
    #pragma unroll
    for (int nb = 0; nb < 8; nb++)
        #pragma unroll
        for (int q = 0; q < 4; q++) acc[nb][q] = 0.f;

    int ch0 = (t == 0) ? 32 : ((t == 1) ? 16 : 0);
    int half = (48 - ch0) >> 1;
    int chS = ch0 + half*kh;
    int chE = kh ? 48 : (ch0 + half);

    const int crow = tid >> 2, cq = tid & 3;
    const int crow2 = (tid + 128) >> 2, cq2 = (tid + 128) & 3;

    // ---- prologue: issue chunks chS, chS+1 ----
    #pragma unroll
    for (int p = 0; p < 2; p++) {
        int pch = chS + p;
        uint32_t stoff = (pch % 3)*ST_SZ;
        size_t g1 = (size_t)crow*NM + pch*32 + cq*8;
        size_t g2 = (size_t)crow2*NM + pch*32 + cq2*8;
        uint32_t s1 = stoff + (uint32_t)(crow*APITCH + cq*8)*2;
        uint32_t s2 = stoff + (uint32_t)(crow2*APITCH + cq2*8)*2;
        CP_ASYNC16(sb + OFF_AHI + s1, Ahig + g1);
        CP_ASYNC16(sb + OFF_ALO + s1, Alog + g1);
        CP_ASYNC16(sb + OFF_BHI + s1, Bhig + g1);
        CP_ASYNC16(sb + OFF_BLO + s1, Blog + g1);
        CP_ASYNC16(sb + OFF_AHI + s2, Ahig + g2);
        CP_ASYNC16(sb + OFF_ALO + s2, Alog + g2);
        CP_ASYNC16(sb + OFF_BHI + s2, Bhig + g2);
        CP_ASYNC16(sb + OFF_BLO + s2, Blog + g2);
        CP_COMMIT();
    }

    int lj = lane >> 3, li = lane & 7;

    for (int ch = chS; ch < chE; ch++) {
        int stC = ch % 3;
        if (ch + 2 < chE) {
            int nch = ch + 2;
            uint32_t stoff = (nch % 3)*ST_SZ;
            size_t g1 = (size_t)crow*NM + nch*32 + cq*8;
            size_t g2 = (size_t)crow2*NM + nch*32 + cq2*8;
            uint32_t s1 = stoff + (uint32_t)(crow*APITCH + cq*8)*2;
            uint32_t s2 = stoff + (uint32_t)(crow2*APITCH + cq2*8)*2;
            CP_ASYNC16(sb + OFF_AHI + s1, Ahig + g1);
            CP_ASYNC16(sb + OFF_ALO + s1, Alog + g1);
            CP_ASYNC16(sb + OFF_BHI + s1, Bhig + g1);
            CP_ASYNC16(sb + OFF_BLO + s1, Blog + g1);
            CP_ASYNC16(sb + OFF_AHI + s2, Ahig + g2);
            CP_ASYNC16(sb + OFF_ALO + s2, Alog + g2);
            CP_ASYNC16(sb + OFF_BHI + s2, Bhig + g2);
            CP_ASYNC16(sb + OFF_BLO + s2, Blog + g2);
            CP_COMMIT();
        }
        if (ch + 2 < chE) CP_WAIT1(); else CP_WAIT0();
        __syncthreads();
        uint32_t baseAH = sb + OFF_AHI + stC*ST_SZ;
        uint32_t baseAL = sb + OFF_ALO + stC*ST_SZ;
        uint32_t baseBH = sb + OFF_BHI + stC*ST_SZ;
        uint32_t baseBL = sb + OFF_BLO + stC*ST_SZ;
        #pragma unroll
        for (int ks = 0; ks < 32; ks += 16) {
            uint32_t bh[8][2], bl[8][2];
            #pragma unroll
            for (int nbp = 0; nbp < 4; nbp++) {
                int nrow = (nbp*2 + (lj>>1))*8 + li;
                int col  = ks + ((lj&1)<<3);
                uint32_t addr = (uint32_t)(nrow*APITCH + col)*2;
                ldmx4(bh[nbp*2][0], bh[nbp*2][1], bh[nbp*2+1][0], bh[nbp*2+1][1], baseBH + addr);
                ldmx4(bl[nbp*2][0], bl[nbp*2][1], bl[nbp*2+1][0], bl[nbp*2+1][1], baseBL + addr);
            }
            int ar = wid*16 + ((lj&1)<<3) + li;
            int ac = ks + ((lj>>1)<<3);
            uint32_t addr = (uint32_t)(ar*APITCH + ac)*2;
            uint32_t ah[4], al[4];
            ldmx4(ah[0], ah[1], ah[2], ah[3], baseAH + addr);
            ldmx4(al[0], al[1], al[2], al[3], baseAL + addr);
            #pragma unroll
            for (int nb = 0; nb < 8; nb++) {
                mma16816(acc[nb], ah, bh[nb]);
                mma16816(acc[nb], ah, bl[nb]);
                mma16816(acc[nb], al, bh[nb]);
            }
        }
    }
    __syncthreads();   // mainloop done; smem repurposed for Us

    // ---- stage u tile in Us, coalesced partial writeback ----
    {
        float* Us = (float*)(smem + OFF_US);
        int r0 = wid*16 + (lane>>2);
        int c0 = (lane&3)*2;
        #pragma unroll
        for (int nb = 0; nb < 8; nb++) {
            int cc = nb*8 + c0;
            Us[r0*USP + cc]       = acc[nb][0];
            Us[r0*USP + cc+1]     = acc[nb][1];
            Us[(r0+8)*USP + cc]   = acc[nb][2];
            Us[(r0+8)*USP + cc+1] = acc[nb][3];
        }
    }
    __syncthreads();
    {
        const float* Us = (const float*)(smem + OFF_US);
        float* up = g_upart[kh];
        #pragma unroll
        for (int s = 0; s < 8; s++) {
            int idx = tid + s*128;
            int r = idx >> 4, q4 = idx & 15;
            float4 v = *(const float4*)(Us + r*USP + q4*4);
            *(float4*)(up + ((size_t)((b*NT+t)*NV) + m0 + r)*NC + q4*4) = v;
        }
    }
}

// ========== gate: u = up0+up1; g = u@Wg + sape@Wsp + tape@Wtp + bg ===========
__global__ void __launch_bounds__(128) k_gate4(const float* __restrict__ sape,
                                               const float* __restrict__ tape,
                                               const float* __restrict__ Wg,
                                               const float* __restrict__ bg,
                                               const float* __restrict__ Wsp,
                                               const float* __restrict__ Wtp, int l) {
    __shared__ float te_s[128];
    __shared__ __align__(16) float Us[64*USP];
    __shared__ __align__(16) float Hs[64*68];
    #define HSP2 68
    float* hout = g_hT[l+1];
    int b  = blockIdx.z;
    int t  = blockIdx.x;
    int m0 = blockIdx.y * 64;
    int tid = threadIdx.x;

    // te = bg + tape@Wtp
    {
        float a = bg[l*128 + tid];
        #pragma unroll
        for (int dd = 0; dd < ND; dd++)
            a += tape[(b*NT+t)*ND + dd] * Wtp[(l*ND + dd)*128 + tid];
        te_s[tid] = a;
    }
    // load u = up0 + up1, plus sape ext cols
    {
        const float* up0 = g_upart[0] + ((size_t)((b*NT+t)*NV) + m0)*NC;
        const float* up1 = g_upart[1] + ((size_t)((b*NT+t)*NV) + m0)*NC;
        #pragma unroll
        for (int s = 0; s < 8; s++) {
            int idx = tid + s*128;
            int r = idx >> 4, q4 = idx & 15;
            float4 a = *(const float4*)(up0 + (size_t)r*NC + q4*4);
            float4 c = *(const float4*)(up1 + (size_t)r*NC + q4*4);
            a.x += c.x; a.y += c.y; a.z += c.z; a.w += c.w;
            *(float4*)(Us + r*USP + q4*4) = a;
        }
        #pragma unroll
        for (int s = 0; s < 4; s++) {
            int idx = tid + s*128;
            int jj = idx >> 3, dd = idx & 7;
            Us[jj*USP + 64 + dd] = sape[(m0+jj)*ND + dd];
        }
    }
    __syncthreads();

    // gate
    {
        int tx = tid & 15;
        int ty = tid >> 4;
        float accL[8][4] = {}, accR[8][4] = {};
        const float* wg = Wg + l*NC*128;
        #pragma unroll 4
        for (int c = 0; c < NC; c++) {
            float4 wl = *(const float4*)(wg + c*128 + tx*4);
            float4 wr = *(const float4*)(wg + c*128 + 64 + tx*4);
            #pragma unroll
            for (int jj = 0; jj < 8; jj++) {
                float uv = Us[(ty*8+jj)*USP + c];
                accL[jj][0] += uv*wl.x; accL[jj][1] += uv*wl.y;
                accL[jj][2] += uv*wl.z; accL[jj][3] += uv*wl.w;
                accR[jj][0] += uv*wr.x; accR[jj][1] += uv*wr.y;
                accR[jj][2] += uv*wr.z; accR[jj][3] += uv*wr.w;
            }
        }
        const float* wsp = Wsp + l*ND*128;
        #pragma unroll
        for (int dd = 0; dd < ND; dd++) {
            float4 wl = *(const float4*)(wsp + dd*128 + tx*4);
            float4 wr = *(const float4*)(wsp + dd*128 + 64 + tx*4);
            #pragma unroll
            for (int jj = 0; jj < 8; jj++) {
                float uv = Us[(ty*8+jj)*USP + 64 + dd];
                accL[jj][0] += uv*wl.x; accL[jj][1] += uv*wl.y;
                accL[jj][2] += uv*wl.z; accL[jj][3] += uv*wl.w;
                accR[jj][0] += uv*wr.x; accR[jj][1] += uv*wr.y;
                accR[jj][2] += uv*wr.z; accR[jj][3] += uv*wr.w;
            }
        }
        float tel[4] = {te_s[tx*4], te_s[tx*4+1], te_s[tx*4+2], te_s[tx*4+3]};
        float ter[4] = {te_s[64+tx*4], te_s[64+tx*4+1], te_s[64+tx*4+2], te_s[64+tx*4+3]};
        #pragma unroll
        for (int jj = 0; jj < 8; jj++) {
            int j = ty*8 + jj;
            #pragma unroll
            for (int q = 0; q < 4; q++) {
                float hv = (accL[jj][q] + tel[q]) * sigm(accR[jj][q] + ter[q]);
                Hs[(tx*4+q)*HSP2 + j] = hv;
            }
        }
    }
    __syncthreads();
    // writeback: h (fp32) + next layer's B splits into parity (l+1)&1
    {
        __nv_bfloat16* BhiN = g_Bhi[(l+1) & 1];
        __nv_bfloat16* BloN = g_Blo[(l+1) & 1];
        float ep3[NTS]; int tout3[NTS];
        if (l < NL-1) {
            #pragma unroll
            for (int kw = 0; kw < NTS; kw++) {
                int tout = t + 2 - kw;
                tout3[kw] = tout;
                ep3[kw] = (tout < NT) ? g_ept[(l+1)*NB*NT*NTS + (b*NT + tout)*NTS + kw] : 0.f;
            }
        }
        #pragma unroll
        for (int s = 0; s < 8; s++) {
            int idx = tid + s*128;
            int r = idx >> 4, q4 = idx & 15;
            float4 v = *(const float4*)(Hs + r*HSP2 + q4*4);
            *(float4*)(hout + ((size_t)((b*NT+t)*NC + r))*NV + m0 + q4*4) = v;
            if (l < NL-1) {
                #pragma unroll
                for (int kw = 0; kw < NTS; kw++) {
                    if (tout3[kw] < NT) {
                        float ep = ep3[kw];
                        union { __nv_bfloat16 h[4]; uint2 u; } Hi, Lo;
                        bsplit(ep*v.x, Hi.h[0], Lo.h[0]);
                        bsplit(ep*v.y, Hi.h[1], Lo.h[1]);
                        bsplit(ep*v.z, Hi.h[2], Lo.h[2]);
                        bsplit(ep*v.w, Hi.h[3], Lo.h[3]);
                        size_t off = ((size_t)(b*NT + tout3[kw])*NC + r)*NM + kw*512 + m0 + q4*4;
                        *(uint2*)(BhiN + off) = Hi.u;
                        *(uint2*)(BloN + off) = Lo.u;
                    }
                }
            }
        }
    }
}

// ---- GFS (time conv) + GLU1 -> skips, all 4 layers at once ----
__global__ void __launch_bounds__(128) k_gfs_all(const float* __restrict__ fs_b,
                                                 const float* __restrict__ g1b) {
    int l = blockIdx.y;
    const float* hcur = g_hT[l+1];
    int b  = blockIdx.x >> 6;
    int v0 = (blockIdx.x & 63) << 3;
    __shared__ float hs[8][NN+4];
    __shared__ float red[2][NC][8];
    __shared__ float ysh[8][NC];
    __shared__ float zsh[8][2*NC];
    int tid = threadIdx.x;
    for (int idx = tid; idx < 8*NN; idx += 128) {
        int vv = idx & 7;
        int c  = (idx >> 3) & 63;
        int t  = idx >> 9;
        hs[vv][t*NC + c] = hcur[((size_t)((b*NT+t)*NC + c))*NV + v0 + vv];
    }
    __syncthreads();
    int oo = tid & 63, half = tid >> 6;
    const float* fwT = g_fswT + l*NN*NC;
    float part[8] = {};
    for (int c = half*32; c < half*32 + 32; c++) {
        #pragma unroll
        for (int t = 0; t < NT; t++) {
            float w = fwT[(c*NT + t)*NC + oo];
            #pragma unroll
            for (int vv = 0; vv < 8; vv++) part[vv] += hs[vv][t*NC + c]*w;
        }
    }
    #pragma unroll
    for (int vv = 0; vv < 8; vv++) red[half][oo][vv] = part[vv];
    __syncthreads();
    if (half == 0) {
        float fb = fs_b[l*NC + oo];
        #pragma unroll
        for (int vv = 0; vv < 8; vv++) ysh[vv][oo] = red[0][oo][vv] + red[1][oo][vv] + fb;
    }
    __syncthreads();
    const float* gT = g_g1wT + l*NC*2*NC;
    float zacc[8];
    float zb = g1b[l*2*NC + tid];
    #pragma unroll
    for (int vv = 0; vv < 8; vv++) zacc[vv] = zb;
    for (int c = 0; c < NC; c++) {
        float w = gT[c*128 + tid];
        #pragma unroll
        for (int vv = 0; vv < 8; vv++) zacc[vv] += ysh[vv][c]*w;
    }
    #pragma unroll
    for (int vv = 0; vv < 8; vv++) zsh[vv][tid] = zacc[vv];
    __syncthreads();
    if (tid < NC) {
        #pragma unroll
        for (int vv = 0; vv < 8; vv++) {
            float zl = zsh[vv][tid], zr = zsh[vv][tid+NC];
            g_skips[(size_t)(b*NV + v0+vv)*256 + l*NC + tid] = zl * sigm(zr);
        }
    }
}

// ---- output GLU + head ----
__global__ void __launch_bounds__(256) k_out(const float* __restrict__ gout_b,
                                             const float* __restrict__ out_b,
                                             float* __restrict__ out) {
    int b  = blockIdx.x >> 5;
    int v0 = (blockIdx.x & 31) << 4;
    __shared__ float sin_[256][16];
    __shared__ float ssh[256][16];
    int tid = threadIdx.x;
    for (int idx = tid; idx < 256*16; idx += 256) {
        int vv = idx >> 8, ch = idx & 255;
        sin_[ch][vv] = g_skips[(size_t)(b*NV + v0+vv)*256 + ch];
    }
    __syncthreads();
    int o = tid;
    float a0[16] = {}, a1[16] = {};
    for (int c = 0; c < 256; c++) {
        float w0 = g_goutT[c*512 + o];
        float w1 = g_goutT[c*512 + o + 256];
        #pragma unroll
        for (int vv = 0; vv < 16; vv++) {
            float s = sin_[c][vv];
            a0[vv] += w0*s; a1[vv] += w1*s;
        }
    }
    float b0 = gout_b[o], b1 = gout_b[o+256];
    #pragma unroll
    for (int vv = 0; vv < 16; vv++) ssh[o][vv] = (a0[vv]+b0) * sigm(a1[vv]+b1);
    __syncthreads();
    if (tid < NP*16) {
        int p = tid >> 4, vv = tid & 15;
        float a = out_b[p];
        for (int c = 0; c < 256; c++) a += ssh[c][vv]*g_outT[c*NP + p];
        out[(b*NP + p)*NV + v0 + vv] = a;
    }
}

extern "C" void kernel_launch(void* const* d_in, const int* in_sizes, int n_in,
                              void* d_out, int out_size) {
    const float* x      = (const float*)d_in[0];
    const float* sape   = (const float*)d_in[1];
    const float* tape   = (const float*)d_in[2];
    const float* srpe   = (const float*)d_in[3];
    const float* trpe   = (const float*)d_in[4];
    const float* mask   = (const float*)d_in[7];
    const float* Wi     = (const float*)d_in[8];
    const float* bi     = (const float*)d_in[9];
    const float* gc_mu  = (const float*)d_in[10];
    const float* gc_sig = (const float*)d_in[11];
    const float* Wg     = (const float*)d_in[12];
    const float* bg     = (const float*)d_in[13];
    const float* Wsp    = (const float*)d_in[14];
    const float* Wtp    = (const float*)d_in[15];
    const float* fs_w   = (const float*)d_in[16];
    const float* fs_b   = (const float*)d_in[17];
    const float* g1w    = (const float*)d_in[18];
    const float* g1b    = (const float*)d_in[19];
    const float* goutw  = (const float*)d_in[20];
    const float* goutb  = (const float*)d_in[21];
    const float* outw   = (const float*)d_in[22];
    const float* outb   = (const float*)d_in[23];
    float* out = (float*)d_out;

    cudaFuncSetAttribute(k_gconv_mma, cudaFuncAttributeMaxDynamicSharedMemorySize, SMEM_TOTAL);

    k_ebase2<<<dim3(1024, NL), 256>>>(srpe, sape, tape, trpe, gc_mu, gc_sig);
    k_init<<<6144 + 1420, 256>>>(x, Wi, bi, fs_w, g1w, goutw, outw);
    k_asplit<<<3072, 256>>>(mask);
    for (int l = 0; l < NL; l++) {
        dim3 gg(NT, NV/64, NB*2);   // (12, 8, 8) = 768 CTAs (split-K)
        k_gconv_mma<<<gg, 128, SMEM_TOTAL>>>(l);
        dim3 gt(NT, NV/64, NB);     // (12, 8, 4) = 384 CTAs
        k_gate4<<<gt, 128>>>(sape, tape, Wg, bg, Wsp, Wtp, l);
    }
    k_gfs_all<<<dim3(NB*NV/8, NL), 128>>>(fs_b, g1b);
    k_out<<<NB*NV/16, 256>>>(goutb, outb, out);
}

// round 17
// speedup vs baseline: 1.0605x; 1.0605x over previous
#include <cuda_runtime.h>
#include <cuda_bf16.h>
#include <cstdint>
#include <math.h>

// ---- problem constants ----
#define NB 4
#define NT 12
#define NV 512
#define NC 64
#define ND 8
#define NTS 3
#define NP 12
#define NL 4
#define NM (NTS*NV)   // 1536
#define NN (NT*NC)    // 768

// ---- scratch (device globals) ----
__device__ float g_hT[NL+1][NB*NT*NC*NV]; // h per layer, transposed [b][t][c][v]
__device__ float g_EbT[NL*NV*NV];         // [l][j][i]
__device__ float g_ept[NL*NB*NT*NTS];
__device__ float g_skips[NB*NV*4*NC];
__device__ float g_fswT[NL*NN*NC];
__device__ float g_g1wT[NL*NC*2*NC];
__device__ float g_goutT[256*512];
__device__ float g_outT[256*NP];
__device__ float g_upart[2][(size_t)NB*NT*NV*NC];         // split-K partial u
__device__ int   g_ticket[NB*NT*8];                       // split-K arrival tickets (parity)
__device__ __nv_bfloat16 g_Ahi[(size_t)NL*NB*NV*NM];      // split A = mask*EbT
__device__ __nv_bfloat16 g_Alo[(size_t)NL*NB*NV*NM];
__device__ __nv_bfloat16 g_Bhi[2][(size_t)NB*NT*NC*NM];   // B = ept*h, parity by layer
__device__ __nv_bfloat16 g_Blo[2][(size_t)NB*NT*NC*NM];

__device__ __forceinline__ float sigm(float x) { return 1.0f/(1.0f+expf(-x)); }

__device__ __forceinline__ uint32_t smem_u32(const void* p) {
    uint32_t a;
    asm("{ .reg .u64 tmp; cvta.to.shared.u64 tmp, %1; cvt.u32.u64 %0, tmp; }"
        : "=r"(a) : "l"(p));
    return a;
}
__device__ __forceinline__ void ldmx4(uint32_t& r0, uint32_t& r1, uint32_t& r2, uint32_t& r3,
                                      uint32_t addr) {
    asm volatile("ldmatrix.sync.aligned.m8n8.x4.shared.b16 {%0,%1,%2,%3}, [%4];"
        : "=r"(r0), "=r"(r1), "=r"(r2), "=r"(r3) : "r"(addr));
}
__device__ __forceinline__ void mma16816(float* c, const uint32_t* a, const uint32_t* b) {
    asm volatile("mma.sync.aligned.m16n8k16.row.col.f32.bf16.bf16.f32 "
        "{%0,%1,%2,%3}, {%4,%5,%6,%7}, {%8,%9}, {%0,%1,%2,%3};"
        : "+f"(c[0]), "+f"(c[1]), "+f"(c[2]), "+f"(c[3])
        : "r"(a[0]), "r"(a[1]), "r"(a[2]), "r"(a[3]), "r"(b[0]), "r"(b[1]));
}
#define CP_ASYNC16(saddr, gptr) \
    asm volatile("cp.async.cg.shared.global [%0], [%1], 16;" :: "r"(saddr), "l"(gptr))
#define CP_COMMIT() asm volatile("cp.async.commit_group;" ::: "memory")
#define CP_WAIT1()  asm volatile("cp.async.wait_group 1;" ::: "memory")
#define CP_WAIT0()  asm volatile("cp.async.wait_group 0;" ::: "memory")

__device__ __forceinline__ void bsplit(float val, __nv_bfloat16& hi, __nv_bfloat16& lo) {
    hi = __float2bfloat16(val);
    lo = __float2bfloat16(val - __bfloat162float(hi));
}

// ---- merged: weight transposes + input layer (+ layer-0 B split, parity 0) ----
__global__ void k_init(const float* __restrict__ x, const float* __restrict__ Wi,
                       const float* __restrict__ bi,
                       const float* __restrict__ fs_w, const float* __restrict__ g1w,
                       const float* __restrict__ gout_w, const float* __restrict__ out_w) {
    if (blockIdx.x < 6144) {
        int idx = blockIdx.x*256 + threadIdx.x;
        int v = idx & 511;
        int c = (idx >> 9) & 63;
        int bt = idx >> 15;
        float h = x[bt*NV + v]*Wi[c] + bi[c];
        g_hT[0][idx] = h;
        int t = bt % NT, b = bt / NT;
        #pragma unroll
        for (int kw = 0; kw < NTS; kw++) {
            int tout = t + 2 - kw;
            if (tout < NT) {
                float ep = g_ept[(b*NT + tout)*NTS + kw];   // layer 0
                __nv_bfloat16 hi, lo;
                bsplit(ep*h, hi, lo);
                size_t off = ((size_t)(b*NT + tout)*NC + c)*NM + kw*512 + v;
                g_Bhi[0][off] = hi;
                g_Blo[0][off] = lo;
            }
        }
        return;
    }
    int idx = (blockIdx.x - 6144)*256 + threadIdx.x;
    if (idx < NL*NN*NC) {
        int l = idx / (NN*NC); int r = idx % (NN*NC); int ct = r >> 6; int oo = r & 63;
        g_fswT[idx] = fs_w[l*NC*NN + oo*NN + ct];
        return;
    }
    idx -= NL*NN*NC;
    if (idx < NL*NC*2*NC) {
        int l = idx / (NC*2*NC); int r = idx % (NC*2*NC); int c = r >> 7; int o = r & 127;
        g_g1wT[idx] = g1w[l*2*NC*NC + o*NC + c];
        return;
    }
    idx -= NL*NC*2*NC;
    if (idx < 256*512) {
        int c = idx >> 9; int o = idx & 511;
        g_goutT[idx] = gout_w[o*256 + c];
        return;
    }
    idx -= 256*512;
    if (idx < 256*NP) {
        int c = idx / NP; int p = idx % NP;
        g_outT[idx] = out_w[p*256 + c];
    }
}

// ---- merged: Ebase^T + (block 0) ept for all layers ----
__global__ void k_ebase2(const float* __restrict__ srpe, const float* __restrict__ sape,
                         const float* __restrict__ tape, const float* __restrict__ trpe,
                         const float* __restrict__ gc_mu, const float* __restrict__ gc_sig) {
    int l = blockIdx.y;
    int tid = threadIdx.x;
    int idx = blockIdx.x*256 + tid;
    int i = idx >> 9, j = idx & 511;
    const float* mu = gc_mu + l*6*ND;
    const float* sg = gc_sig + l*6*ND;
    float gs0 = 0.f, gs1 = 0.f, a = 0.f;
    const float* e = srpe + (size_t)idx*ND;
    #pragma unroll
    for (int dd = 0; dd < ND; dd++) {
        float e0 = sape[i*ND + dd] - mu[0*ND+dd];
        float e1 = sape[j*ND + dd] - mu[1*ND+dd];
        float e4 = e[dd] - mu[4*ND+dd];
        gs0 += -0.5f*e0*e0*sg[0*ND+dd]*sg[0*ND+dd];
        gs1 += -0.5f*e1*e1*sg[1*ND+dd]*sg[1*ND+dd];
        a   += -0.5f*e4*e4*sg[4*ND+dd]*sg[4*ND+dd];
    }
    g_EbT[l*NV*NV + j*NV + i] = expf(a + gs0 + gs1);

    if (blockIdx.x == 0) {
        __shared__ float gt2[NB*NT];
        __shared__ float gt3[NB*(NT+2)];
        __shared__ float gt5[NTS];
        if (tid < NB*NT) {
            float s = 0.f;
            #pragma unroll
            for (int dd = 0; dd < ND; dd++) {
                float dv = tape[tid*ND + dd] - mu[2*ND+dd];
                s += -0.5f*dv*dv*sg[2*ND+dd]*sg[2*ND+dd];
            }
            gt2[tid] = s;
        }
        if (tid < NB*(NT+2)) {
            int b = tid/(NT+2), tau = tid%(NT+2);
            float s = 0.f;
            #pragma unroll
            for (int dd = 0; dd < ND; dd++) {
                float ev = (tau < 2) ? 0.0f : tape[(b*NT + (tau-2))*ND + dd];
                float dv = ev - mu[3*ND+dd];
                s += -0.5f*dv*dv*sg[3*ND+dd]*sg[3*ND+dd];
            }
            gt3[tid] = s;
        }
        if (tid < NTS) {
            float s = 0.f;
            #pragma unroll
            for (int dd = 0; dd < ND; dd++) {
                float dv = trpe[tid*ND + dd] - mu[5*ND+dd];
                s += -0.5f*dv*dv*sg[5*ND+dd]*sg[5*ND+dd];
            }
            gt5[tid] = s;
        }
        __syncthreads();
        if (tid < NB*NT*NTS) {
            int k = tid % NTS; int bt = tid / NTS;
            int b = bt / NT, t = bt % NT;
            g_ept[l*NB*NT*NTS + tid] = expf(gt2[bt] + gt3[b*(NT+2) + t + k] + gt5[k]);
        }
    }
}

// ---- split A = mask*EbT into bf16 hi/lo ----
__global__ void k_asplit(const float* __restrict__ mask) {
    size_t gidx = (size_t)blockIdx.x*256 + threadIdx.x;
    size_t g = gidx;
    int mq = (int)(g % 384); g /= 384;
    int j  = (int)(g % 512);
    int b  = (int)(g / 512);
    int m = mq*4, i = m & 511;
    float4 mv = *(const float4*)(mask + (((size_t)b*NV + j)*NM + m));
    #pragma unroll
    for (int l = 0; l < NL; l++) {
        float4 ev = *(const float4*)(g_EbT + ((size_t)l*NV + j)*NV + i);
        float a[4] = {mv.x*ev.x, mv.y*ev.y, mv.z*ev.z, mv.w*ev.w};
        union { __nv_bfloat16 h[4]; uint2 u; } Hi, Lo;
        #pragma unroll
        for (int q = 0; q < 4; q++) bsplit(a[q], Hi.h[q], Lo.h[q]);
        size_t off = (((size_t)l*NB + b)*NV + j)*NM + m;
        *(uint2*)(g_Ahi + off) = Hi.u;
        *(uint2*)(g_Alo + off) = Lo.u;
    }
}

// ===== split-K pipelined warp-MMA graph-conv + ticketed fused gate ==========
#define APITCH 40
#define ST_SZ 5120
#define OFF_TE    0
#define OFF_AHI   512
#define OFF_ALO   15872
#define OFF_BHI   31232
#define OFF_BLO   46592
#define OFF_US    512
#define OFF_HS    20480
#define SMEM_TOTAL 61952
#define USP 76
#define HSP 68

__global__ void __launch_bounds__(128, 3) k_gconv_mma(const float* __restrict__ sape,
                                                      const float* __restrict__ tape,
                                                      const float* __restrict__ Wg,
                                                      const float* __restrict__ bg,
                                                      const float* __restrict__ Wsp,
                                                      const float* __restrict__ Wtp, int l) {
    extern __shared__ __align__(1024) char smem[];
    int bz = blockIdx.z;
    int b  = bz & 3;
    int kh = bz >> 2;
    int t  = blockIdx.x;
    int m0 = blockIdx.y * 64;
    int tid = threadIdx.x, wid = tid >> 5, lane = tid & 31;
    uint32_t sb = smem_u32(smem);

    const __nv_bfloat16* Ahig = g_Ahi + (((size_t)l*NB + b)*NV + m0)*NM;
    const __nv_bfloat16* Alog = g_Alo + (((size_t)l*NB + b)*NV + m0)*NM;
    const __nv_bfloat16* Bhig = g_Bhi[l & 1] + ((size_t)(b*NT + t)*NC)*NM;
    const __nv_bfloat16* Blog = g_Blo[l & 1] + ((size_t)(b*NT + t)*NC)*NM;

    float acc[8][4];
    #pragma unroll
    for (int nb = 0; nb < 8; nb++)
        #pragma unroll
        for (int q = 0; q < 4; q++) acc[nb][q] = 0.f;

    int ch0 = (t == 0) ? 32 : ((t == 1) ? 16 : 0);
    int half = (48 - ch0) >> 1;
    int chS = ch0 + half*kh;
    int chE = kh ? 48 : (ch0 + half);

    const int crow = tid >> 2, cq = tid & 3;
    const int crow2 = (tid + 128) >> 2, cq2 = (tid + 128) & 3;

    // ---- prologue: issue chunks chS, chS+1 ----
    #pragma unroll
    for (int p = 0; p < 2; p++) {
        int pch = chS + p;
        uint32_t stoff = (pch % 3)*ST_SZ;
        size_t g1 = (size_t)crow*NM + pch*32 + cq*8;
        size_t g2 = (size_t)crow2*NM + pch*32 + cq2*8;
        uint32_t s1 = stoff + (uint32_t)(crow*APITCH + cq*8)*2;
        uint32_t s2 = stoff + (uint32_t)(crow2*APITCH + cq2*8)*2;
        CP_ASYNC16(sb + OFF_AHI + s1, Ahig + g1);
        CP_ASYNC16(sb + OFF_ALO + s1, Alog + g1);
        CP_ASYNC16(sb + OFF_BHI + s1, Bhig + g1);
        CP_ASYNC16(sb + OFF_BLO + s1, Blog + g1);
        CP_ASYNC16(sb + OFF_AHI + s2, Ahig + g2);
        CP_ASYNC16(sb + OFF_ALO + s2, Alog + g2);
        CP_ASYNC16(sb + OFF_BHI + s2, Bhig + g2);
        CP_ASYNC16(sb + OFF_BLO + s2, Blog + g2);
        CP_COMMIT();
    }

    int lj = lane >> 3, li = lane & 7;

    for (int ch = chS; ch < chE; ch++) {
        int stC = ch % 3;
        if (ch + 2 < chE) {
            int nch = ch + 2;
            uint32_t stoff = (nch % 3)*ST_SZ;
            size_t g1 = (size_t)crow*NM + nch*32 + cq*8;
            size_t g2 = (size_t)crow2*NM + nch*32 + cq2*8;
            uint32_t s1 = stoff + (uint32_t)(crow*APITCH + cq*8)*2;
            uint32_t s2 = stoff + (uint32_t)(crow2*APITCH + cq2*8)*2;
            CP_ASYNC16(sb + OFF_AHI + s1, Ahig + g1);
            CP_ASYNC16(sb + OFF_ALO + s1, Alog + g1);
            CP_ASYNC16(sb + OFF_BHI + s1, Bhig + g1);
            CP_ASYNC16(sb + OFF_BLO + s1, Blog + g1);
            CP_ASYNC16(sb + OFF_AHI + s2, Ahig + g2);
            CP_ASYNC16(sb + OFF_ALO + s2, Alog + g2);
            CP_ASYNC16(sb + OFF_BHI + s2, Bhig + g2);
            CP_ASYNC16(sb + OFF_BLO + s2, Blog + g2);
            CP_COMMIT();
        }
        if (ch + 2 < chE) CP_WAIT1(); else CP_WAIT0();
        __syncthreads();
        uint32_t baseAH = sb + OFF_AHI + stC*ST_SZ;
        uint32_t baseAL = sb + OFF_ALO + stC*ST_SZ;
        uint32_t baseBH = sb + OFF_BHI + stC*ST_SZ;
        uint32_t baseBL = sb + OFF_BLO + stC*ST_SZ;
        #pragma unroll
        for (int ks = 0; ks < 32; ks += 16) {
            uint32_t bh[8][2], bl[8][2];
            #pragma unroll
            for (int nbp = 0; nbp < 4; nbp++) {
                int nrow = (nbp*2 + (lj>>1))*8 + li;
                int col  = ks + ((lj&1)<<3);
                uint32_t addr = (uint32_t)(nrow*APITCH + col)*2;
                ldmx4(bh[nbp*2][0], bh[nbp*2][1], bh[nbp*2+1][0], bh[nbp*2+1][1], baseBH + addr);
                ldmx4(bl[nbp*2][0], bl[nbp*2][1], bl[nbp*2+1][0], bl[nbp*2+1][1], baseBL + addr);
            }
            int ar = wid*16 + ((lj&1)<<3) + li;
            int ac = ks + ((lj>>1)<<3);
            uint32_t addr = (uint32_t)(ar*APITCH + ac)*2;
            uint32_t ah[4], al[4];
            ldmx4(ah[0], ah[1], ah[2], ah[3], baseAH + addr);
            ldmx4(al[0], al[1], al[2], al[3], baseAL + addr);
            #pragma unroll
            for (int nb = 0; nb < 8; nb++) {
                mma16816(acc[nb], ah, bh[nb]);
                mma16816(acc[nb], ah, bl[nb]);
                mma16816(acc[nb], al, bh[nb]);
            }
        }
    }
    __syncthreads();   // mainloop done; smem repurposed

    // ---- stage own partial in Us, write to g_upart[kh] ----
    float* Us = (float*)(smem + OFF_US);
    {
        int r0 = wid*16 + (lane>>2);
        int c0 = (lane&3)*2;
        #pragma unroll
        for (int nb = 0; nb < 8; nb++) {
            int cc = nb*8 + c0;
            Us[r0*USP + cc]       = acc[nb][0];
            Us[r0*USP + cc+1]     = acc[nb][1];
            Us[(r0+8)*USP + cc]   = acc[nb][2];
            Us[(r0+8)*USP + cc+1] = acc[nb][3];
        }
    }
    __syncthreads();
    {
        float* up = g_upart[kh];
        #pragma unroll
        for (int s = 0; s < 8; s++) {
            int idx = tid + s*128;
            int r = idx >> 4, q4 = idx & 15;
            float4 v = *(const float4*)(Us + r*USP + q4*4);
            *(float4*)(up + ((size_t)((b*NT+t)*NV) + m0 + r)*NC + q4*4) = v;
        }
    }
    // ---- ticket: second arriver does the reduction + gate ----
    __shared__ int s_sec;
    __threadfence();                    // release own partial
    if (tid == 0) {
        int tile = (b*NT + t)*8 + (m0 >> 6);
        int old = atomicAdd(&g_ticket[tile], 1);
        s_sec = old & 1;                // odd -> second arrival this invocation
    }
    __syncthreads();
    if (!s_sec) return;
    __threadfence();                    // acquire other partial

    // te = bg + tape@Wtp
    {
        float a = bg[l*128 + tid];
        #pragma unroll
        for (int dd = 0; dd < ND; dd++)
            a += tape[(b*NT+t)*ND + dd] * Wtp[(l*ND + dd)*128 + tid];
        ((float*)(smem + OFF_TE))[tid] = a;
    }
    // Us += other partial; fill sape ext cols
    {
        const float* uo = g_upart[kh^1] + ((size_t)((b*NT+t)*NV) + m0)*NC;
        #pragma unroll
        for (int s = 0; s < 8; s++) {
            int idx = tid + s*128;
            int r = idx >> 4, q4 = idx & 15;
            float4 o = *(const float4*)(uo + (size_t)r*NC + q4*4);
            float* dst = Us + r*USP + q4*4;
            dst[0] += o.x; dst[1] += o.y; dst[2] += o.z; dst[3] += o.w;
        }
        #pragma unroll
        for (int s = 0; s < 4; s++) {
            int idx = tid + s*128;
            int jj = idx >> 3, dd = idx & 7;
            Us[jj*USP + 64 + dd] = sape[(m0+jj)*ND + dd];
        }
    }
    __syncthreads();

    // ---- gate: g = u@Wg + sape@Wsp + te; h = gl*sigm(gr) ----
    float* Hs = (float*)(smem + OFF_HS);
    {
        const float* te = (const float*)(smem + OFF_TE);
        int tx = tid & 15;
        int ty = tid >> 4;
        float accL[8][4] = {}, accR[8][4] = {};
        const float* wg = Wg + l*NC*128;
        #pragma unroll 4
        for (int c = 0; c < NC; c++) {
            float4 wl = *(const float4*)(wg + c*128 + tx*4);
            float4 wr = *(const float4*)(wg + c*128 + 64 + tx*4);
            #pragma unroll
            for (int jj = 0; jj < 8; jj++) {
                float uv = Us[(ty*8+jj)*USP + c];
                accL[jj][0] += uv*wl.x; accL[jj][1] += uv*wl.y;
                accL[jj][2] += uv*wl.z; accL[jj][3] += uv*wl.w;
                accR[jj][0] += uv*wr.x; accR[jj][1] += uv*wr.y;
                accR[jj][2] += uv*wr.z; accR[jj][3] += uv*wr.w;
            }
        }
        const float* wsp = Wsp + l*ND*128;
        #pragma unroll
        for (int dd = 0; dd < ND; dd++) {
            float4 wl = *(const float4*)(wsp + dd*128 + tx*4);
            float4 wr = *(const float4*)(wsp + dd*128 + 64 + tx*4);
            #pragma unroll
            for (int jj = 0; jj < 8; jj++) {
                float uv = Us[(ty*8+jj)*USP + 64 + dd];
                accL[jj][0] += uv*wl.x; accL[jj][1] += uv*wl.y;
                accL[jj][2] += uv*wl.z; accL[jj][3] += uv*wl.w;
                accR[jj][0] += uv*wr.x; accR[jj][1] += uv*wr.y;
                accR[jj][2] += uv*wr.z; accR[jj][3] += uv*wr.w;
            }
        }
        float tel[4] = {te[tx*4], te[tx*4+1], te[tx*4+2], te[tx*4+3]};
        float ter[4] = {te[64+tx*4], te[64+tx*4+1], te[64+tx*4+2], te[64+tx*4+3]};
        #pragma unroll
        for (int jj = 0; jj < 8; jj++) {
            int j = ty*8 + jj;
            #pragma unroll
            for (int q = 0; q < 4; q++) {
                float hv = (accL[jj][q] + tel[q]) * sigm(accR[jj][q] + ter[q]);
                Hs[(tx*4+q)*HSP + j] = hv;
            }
        }
    }
    __syncthreads();
    // ---- writeback: h (fp32) + next layer's B splits into parity (l+1)&1 ----
    {
        float* hout = g_hT[l+1];
        __nv_bfloat16* BhiN = g_Bhi[(l+1) & 1];
        __nv_bfloat16* BloN = g_Blo[(l+1) & 1];
        float ep3[NTS]; int tout3[NTS];
        if (l < NL-1) {
            #pragma unroll
            for (int kw = 0; kw < NTS; kw++) {
                int tout = t + 2 - kw;
                tout3[kw] = tout;
                ep3[kw] = (tout < NT) ? g_ept[(l+1)*NB*NT*NTS + (b*NT + tout)*NTS + kw] : 0.f;
            }
        }
        #pragma unroll
        for (int s = 0; s < 8; s++) {
            int idx = tid + s*128;
            int r = idx >> 4, q4 = idx & 15;
            float4 v = *(const float4*)(Hs + r*HSP + q4*4);
            *(float4*)(hout + ((size_t)((b*NT+t)*NC + r))*NV + m0 + q4*4) = v;
            if (l < NL-1) {
                #pragma unroll
                for (int kw = 0; kw < NTS; kw++) {
                    if (tout3[kw] < NT) {
                        float ep = ep3[kw];
                        union { __nv_bfloat16 h[4]; uint2 u; } Hi, Lo;
                        bsplit(ep*v.x, Hi.h[0], Lo.h[0]);
                        bsplit(ep*v.y, Hi.h[1], Lo.h[1]);
                        bsplit(ep*v.z, Hi.h[2], Lo.h[2]);
                        bsplit(ep*v.w, Hi.h[3], Lo.h[3]);
                        size_t off = ((size_t)(b*NT + tout3[kw])*NC + r)*NM + kw*512 + m0 + q4*4;
                        *(uint2*)(BhiN + off) = Hi.u;
                        *(uint2*)(BloN + off) = Lo.u;
                    }
                }
            }
        }
    }
}

// ---- GFS (time conv) + GLU1 -> skips, all 4 layers at once ----
__global__ void __launch_bounds__(128) k_gfs_all(const float* __restrict__ fs_b,
                                                 const float* __restrict__ g1b) {
    int l = blockIdx.y;
    const float* hcur = g_hT[l+1];
    int b  = blockIdx.x >> 6;
    int v0 = (blockIdx.x & 63) << 3;
    __shared__ float hs[8][NN+4];
    __shared__ float red[2][NC][8];
    __shared__ float ysh[8][NC];
    __shared__ float zsh[8][2*NC];
    int tid = threadIdx.x;
    for (int idx = tid; idx < 8*NN; idx += 128) {
        int vv = idx & 7;
        int c  = (idx >> 3) & 63;
        int t  = idx >> 9;
        hs[vv][t*NC + c] = hcur[((size_t)((b*NT+t)*NC + c))*NV + v0 + vv];
    }
    __syncthreads();
    int oo = tid & 63, half = tid >> 6;
    const float* fwT = g_fswT + l*NN*NC;
    float part[8] = {};
    for (int c = half*32; c < half*32 + 32; c++) {
        #pragma unroll
        for (int t = 0; t < NT; t++) {
            float w = fwT[(c*NT + t)*NC + oo];
            #pragma unroll
            for (int vv = 0; vv < 8; vv++) part[vv] += hs[vv][t*NC + c]*w;
        }
    }
    #pragma unroll
    for (int vv = 0; vv < 8; vv++) red[half][oo][vv] = part[vv];
    __syncthreads();
    if (half == 0) {
        float fb = fs_b[l*NC + oo];
        #pragma unroll
        for (int vv = 0; vv < 8; vv++) ysh[vv][oo] = red[0][oo][vv] + red[1][oo][vv] + fb;
    }
    __syncthreads();
    const float* gT = g_g1wT + l*NC*2*NC;
    float zacc[8];
    float zb = g1b[l*2*NC + tid];
    #pragma unroll
    for (int vv = 0; vv < 8; vv++) zacc[vv] = zb;
    for (int c = 0; c < NC; c++) {
        float w = gT[c*128 + tid];
        #pragma unroll
        for (int vv = 0; vv < 8; vv++) zacc[vv] += ysh[vv][c]*w;
    }
    #pragma unroll
    for (int vv = 0; vv < 8; vv++) zsh[vv][tid] = zacc[vv];
    __syncthreads();
    if (tid < NC) {
        #pragma unroll
        for (int vv = 0; vv < 8; vv++) {
            float zl = zsh[vv][tid], zr = zsh[vv][tid+NC];
            g_skips[(size_t)(b*NV + v0+vv)*256 + l*NC + tid] = zl * sigm(zr);
        }
    }
}

// ---- output GLU + head ----
__global__ void __launch_bounds__(256) k_out(const float* __restrict__ gout_b,
                                             const float* __restrict__ out_b,
                                             float* __restrict__ out) {
    int b  = blockIdx.x >> 5;
    int v0 = (blockIdx.x & 31) << 4;
    __shared__ float sin_[256][16];
    __shared__ float ssh[256][16];
    int tid = threadIdx.x;
    for (int idx = tid; idx < 256*16; idx += 256) {
        int vv = idx >> 8, ch = idx & 255;
        sin_[ch][vv] = g_skips[(size_t)(b*NV + v0+vv)*256 + ch];
    }
    __syncthreads();
    int o = tid;
    float a0[16] = {}, a1[16] = {};
    for (int c = 0; c < 256; c++) {
        float w0 = g_goutT[c*512 + o];
        float w1 = g_goutT[c*512 + o + 256];
        #pragma unroll
        for (int vv = 0; vv < 16; vv++) {
            float s = sin_[c][vv];
            a0[vv] += w0*s; a1[vv] += w1*s;
        }
    }
    float b0 = gout_b[o], b1 = gout_b[o+256];
    #pragma unroll
    for (int vv = 0; vv < 16; vv++) ssh[o][vv] = (a0[vv]+b0) * sigm(a1[vv]+b1);
    __syncthreads();
    if (tid < NP*16) {
        int p = tid >> 4, vv = tid & 15;
        float a = out_b[p];
        for (int c = 0; c < 256; c++) a += ssh[c][vv]*g_outT[c*NP + p];
        out[(b*NP + p)*NV + v0 + vv] = a;
    }
}

extern "C" void kernel_launch(void* const* d_in, const int* in_sizes, int n_in,
                              void* d_out, int out_size) {
    const float* x      = (const float*)d_in[0];
    const float* sape   = (const float*)d_in[1];
    const float* tape   = (const float*)d_in[2];
    const float* srpe   = (const float*)d_in[3];
    const float* trpe   = (const float*)d_in[4];
    const float* mask   = (const float*)d_in[7];
    const float* Wi     = (const float*)d_in[8];
    const float* bi     = (const float*)d_in[9];
    const float* gc_mu  = (const float*)d_in[10];
    const float* gc_sig = (const float*)d_in[11];
    const float* Wg     = (const float*)d_in[12];
    const float* bg     = (const float*)d_in[13];
    const float* Wsp    = (const float*)d_in[14];
    const float* Wtp    = (const float*)d_in[15];
    const float* fs_w   = (const float*)d_in[16];
    const float* fs_b   = (const float*)d_in[17];
    const float* g1w    = (const float*)d_in[18];
    const float* g1b    = (const float*)d_in[19];
    const float* goutw  = (const float*)d_in[20];
    const float* goutb  = (const float*)d_in[21];
    const float* outw   = (const float*)d_in[22];
    const float* outb   = (const float*)d_in[23];
    float* out = (float*)d_out;

    cudaFuncSetAttribute(k_gconv_mma, cudaFuncAttributeMaxDynamicSharedMemorySize, SMEM_TOTAL);

    k_ebase2<<<dim3(1024, NL), 256>>>(srpe, sape, tape, trpe, gc_mu, gc_sig);
    k_init<<<6144 + 1420, 256>>>(x, Wi, bi, fs_w, g1w, goutw, outw);
    k_asplit<<<3072, 256>>>(mask);
    for (int l = 0; l < NL; l++) {
        dim3 gg(NT, NV/64, NB*2);   // (12, 8, 8) = 768 CTAs (split-K)
        k_gconv_mma<<<gg, 128, SMEM_TOTAL>>>(sape, tape, Wg, bg, Wsp, Wtp, l);
    }
    k_gfs_all<<<dim3(NB*NV/8, NL), 128>>>(fs_b, g1b);
    k_out<<<NB*NV/16, 256>>>(goutb, outb, out);
}